// round 1
// baseline (speedup 1.0000x reference)
#include <cuda_runtime.h>

// LSTM: B=256, T=2048, F=64, U=10 (4U=40 gates, Keras order i,f,g,o),
// g activation = softsign, cell out = o * softsign(c), head = sigmoid(h@dw+db).

#define BB 256
#define TT 2048
#define FF 64
#define UU 10
#define GG 40

// Scratch: xz = x@W + bias, stored per (b,t) row in UNIT-MAJOR layout:
// row[u*4 + gate], so one float4 per unit = {zi, zf, zg, zo}.  83.9 MB.
__device__ float g_xz[(size_t)BB * TT * GG];

// ---------------------------------------------------------------------------
// Kernel 1: xz[r, perm(col)] = bias[col] + sum_k x[r,k] * W[k,col]
// Block: 40x8 threads, 64 rows of (b,t) per block; W and x tiles in smem.
// ---------------------------------------------------------------------------
__global__ void gemm_xz_kernel(const float* __restrict__ x,
                               const float* __restrict__ W,
                               const float* __restrict__ bias) {
    __shared__ float Wt[GG][FF + 4];   // transposed W, padded (bank-safe float4)
    __shared__ float xs[64][FF + 4];   // x tile, padded

    const int tx = threadIdx.x;        // col 0..39
    const int ty = threadIdx.y;        // 0..7
    const int tid = ty * 40 + tx;

    // Load W[k][col] -> Wt[col][k]
    for (int i = tid; i < FF * GG; i += 320) {
        int k = i / GG, col = i - k * GG;
        Wt[col][k] = W[i];
    }
    // Load 64 rows of x (each row 64 floats = 16 float4)
    const size_t r0 = (size_t)blockIdx.x * 64;
    const float4* x4 = reinterpret_cast<const float4*>(x + r0 * FF);
    for (int i = tid; i < 64 * (FF / 4); i += 320) {
        int row = i >> 4, k4 = i & 15;
        *reinterpret_cast<float4*>(&xs[row][k4 * 4]) = x4[i];
    }
    __syncthreads();

    float acc[8];
    const float bv = bias[tx];
#pragma unroll
    for (int rr = 0; rr < 8; ++rr) acc[rr] = bv;

#pragma unroll
    for (int k4 = 0; k4 < FF / 4; ++k4) {
        const float4 w = *reinterpret_cast<const float4*>(&Wt[tx][k4 * 4]);
#pragma unroll
        for (int rr = 0; rr < 8; ++rr) {
            const float4 xv =
                *reinterpret_cast<const float4*>(&xs[ty * 8 + rr][k4 * 4]);
            acc[rr] = fmaf(xv.x, w.x, acc[rr]);
            acc[rr] = fmaf(xv.y, w.y, acc[rr]);
            acc[rr] = fmaf(xv.z, w.z, acc[rr]);
            acc[rr] = fmaf(xv.w, w.w, acc[rr]);
        }
    }

    // Permuted write: col = gate*10 + u  ->  slot u*4 + gate (unit-major)
    const int u = tx % UU, gate = tx / UU;
    const int oc = u * 4 + gate;
#pragma unroll
    for (int rr = 0; rr < 8; ++rr) {
        g_xz[(r0 + (size_t)ty * 8 + rr) * GG + oc] = acc[rr];
    }
}

// ---------------------------------------------------------------------------
// Kernel 2: sequential LSTM scan. One warp = 3 batches (lanes 0..29 active,
// lane = grp*10 + u). Lane u owns unit u: 4 recurrent columns in registers,
// h broadcast via shfl, no smem / barriers in the T-loop. xz prefetched
// 4 steps ahead as one float4 per lane per step.
// ---------------------------------------------------------------------------
__global__ void lstm_scan_kernel(const float* __restrict__ R,   // [10][40]
                                 const float* __restrict__ dw,  // [10]
                                 const float* __restrict__ db,  // [1]
                                 float* __restrict__ out) {     // [256]
    const int lane = threadIdx.x;
    const int grp = lane / UU;          // 0..3 (grp==3 -> dummy lanes 30,31)
    const int u = lane - grp * UU;      // 0..9
    const int batch = blockIdx.x * 3 + grp;
    const bool valid = (grp < 3) && (batch < BB);
    const int bc = valid ? batch : (BB - 1);   // clamp for safe loads
    const int base = grp * UU;

    float Ri[UU], Rf[UU], Rg[UU], Ro[UU];
#pragma unroll
    for (int j = 0; j < UU; ++j) {
        Ri[j] = R[j * GG + u];
        Rf[j] = R[j * GG + UU + u];
        Rg[j] = R[j * GG + 2 * UU + u];
        Ro[j] = R[j * GG + 3 * UU + u];
    }
    float dwr[UU];
#pragma unroll
    for (int j = 0; j < UU; ++j) dwr[j] = dw[j];

    // Per-lane xz stream: float4 {zi,zf,zg,zo} for unit u, stride UU float4/step
    const float4* xzp =
        reinterpret_cast<const float4*>(g_xz) + (size_t)bc * TT * UU + u;

    float4 buf[4];
#pragma unroll
    for (int p = 0; p < 4; ++p) buf[p] = xzp[(size_t)p * UU];

    float h = 0.f, c = 0.f;

    for (int t = 0; t < TT; t += 4) {
#pragma unroll
        for (int p = 0; p < 4; ++p) {
            const float4 z4 = buf[p];
            const int tf = t + 4 + p;                 // prefetch 4 ahead
            if (tf < TT) buf[p] = xzp[(size_t)tf * UU];

            float zi = z4.x, zf = z4.y, zg = z4.z, zo = z4.w;
#pragma unroll
            for (int j = 0; j < UU; ++j) {
                const float hj = __shfl_sync(0xffffffffu, h, base + j);
                zi = fmaf(hj, Ri[j], zi);
                zf = fmaf(hj, Rf[j], zf);
                zg = fmaf(hj, Rg[j], zg);
                zo = fmaf(hj, Ro[j], zo);
            }
            const float ig = __fdividef(1.f, 1.f + __expf(-zi));
            const float fg = __fdividef(1.f, 1.f + __expf(-zf));
            const float og = __fdividef(1.f, 1.f + __expf(-zo));
            const float gg = __fdividef(zg, 1.f + fabsf(zg));   // softsign
            c = fmaf(fg, c, ig * gg);
            h = og * __fdividef(c, 1.f + fabsf(c));             // o*softsign(c)
        }
    }

    // Head: logit = h @ dw + db, out = sigmoid(logit)
    float logit = db[0];
#pragma unroll
    for (int j = 0; j < UU; ++j)
        logit = fmaf(__shfl_sync(0xffffffffu, h, base + j), dwr[j], logit);
    if (valid && u == 0)
        out[batch] = __fdividef(1.f, 1.f + __expf(-logit));
}

// ---------------------------------------------------------------------------
extern "C" void kernel_launch(void* const* d_in, const int* in_sizes, int n_in,
                              void* d_out, int out_size) {
    const float* x    = (const float*)d_in[0];  // [256,2048,64]
    const float* W    = (const float*)d_in[1];  // [64,40]
    const float* R    = (const float*)d_in[2];  // [10,40]
    const float* bias = (const float*)d_in[3];  // [40]
    const float* dw   = (const float*)d_in[4];  // [10,1]
    const float* db   = (const float*)d_in[5];  // [1]
    float* out = (float*)d_out;                 // [256,1]

    dim3 b1(40, 8);
    gemm_xz_kernel<<<(BB * TT) / 64, b1>>>(x, W, bias);
    lstm_scan_kernel<<<(BB + 2) / 3, 32>>>(R, dw, db, out);
}

// round 2
// speedup vs baseline: 1.1969x; 1.1969x over previous
#include <cuda_runtime.h>

// LSTM: B=256, T=2048, F=64, U=10 (4U=40 gates, Keras order i,f,g,o),
// g activation = softsign, cell out = o * softsign(c), head = sigmoid(h@dw+db).

#define BB 256
#define TT 2048
#define FF 64
#define UU 10
#define GG 40

// Scratch: xz = x@W + bias, per (b,t) row in UNIT-MAJOR layout: row[u*4+gate],
// one float4 per unit = {zi, zf, zg, zo}. Gates i,f,o PRE-SCALED by 0.5 so
// sigmoid(z) = 0.5*tanh(z_scaled) + 0.5.  83.9 MB.
__device__ float g_xz[(size_t)BB * TT * GG];

// ---------------------------------------------------------------------------
// f32x2 packed helpers (sm_103a)
// ---------------------------------------------------------------------------
__device__ __forceinline__ unsigned long long pack2(float x, float y) {
    unsigned long long d;
    asm("mov.b64 %0, {%1, %2};" : "=l"(d) : "f"(x), "f"(y));
    return d;
}
__device__ __forceinline__ void unpack2(unsigned long long a, float& x, float& y) {
    asm("mov.b64 {%0, %1}, %2;" : "=f"(x), "=f"(y) : "l"(a));
}
__device__ __forceinline__ unsigned long long ffma2(unsigned long long a,
                                                    unsigned long long b,
                                                    unsigned long long c) {
    unsigned long long d;
    asm("fma.rn.f32x2 %0, %1, %2, %3;" : "=l"(d) : "l"(a), "l"(b), "l"(c));
    return d;
}
__device__ __forceinline__ unsigned long long fadd2(unsigned long long a,
                                                    unsigned long long b) {
    unsigned long long d;
    asm("add.rn.f32x2 %0, %1, %2;" : "=l"(d) : "l"(a), "l"(b));
    return d;
}
__device__ __forceinline__ float tanh_ap(float x) {
    float r;
    asm("tanh.approx.f32 %0, %1;" : "=f"(r) : "f"(x));
    return r;
}
__device__ __forceinline__ float rcp_ap(float x) {
    float r;
    asm("rcp.approx.f32 %0, %1;" : "=f"(r) : "f"(x));
    return r;
}

// ---------------------------------------------------------------------------
// Kernel 1: xz[r, perm(col)] = sc * (bias[col] + sum_k x[r,k] * W[k,col])
// sc = 0.5 for gates i,f,o (tanh-sigmoid prescale), 1 for g.
// Block: (10,16)=160 thr; thread computes 4 cols x 8 rows; 128 rows/block.
// smem-BW: 12 LDS.128 per 128 FMA = 1.5 B/FMA  (<= 2 B/FMA crossbar budget).
// ---------------------------------------------------------------------------
__global__ void gemm_xz_kernel(const float* __restrict__ x,
                               const float* __restrict__ W,
                               const float* __restrict__ bias) {
    __shared__ float Wt[GG][FF + 4];    // W transposed, padded
    __shared__ float xs[128][FF + 4];   // x tile

    const int tx = threadIdx.x;         // 0..9  -> cols 4tx..4tx+3
    const int ty = threadIdx.y;         // 0..15 -> rows 8ty..8ty+7
    const int tid = ty * 10 + tx;

    for (int i = tid; i < FF * GG; i += 160) {
        int k = i / GG, col = i - k * GG;
        Wt[col][k] = W[i];
    }
    const size_t r0 = (size_t)blockIdx.x * 128;
    const float4* x4 = reinterpret_cast<const float4*>(x + r0 * FF);
    for (int i = tid; i < 128 * (FF / 4); i += 160) {
        int row = i >> 4, k4 = i & 15;
        *reinterpret_cast<float4*>(&xs[row][k4 * 4]) = x4[i];
    }
    __syncthreads();

    const int c0 = tx * 4;
    float acc[4][8];
#pragma unroll
    for (int cc = 0; cc < 4; ++cc) {
        const float bv = bias[c0 + cc];
#pragma unroll
        for (int rr = 0; rr < 8; ++rr) acc[cc][rr] = bv;
    }

#pragma unroll
    for (int k4 = 0; k4 < FF / 4; ++k4) {
        float4 w[4];
#pragma unroll
        for (int cc = 0; cc < 4; ++cc)
            w[cc] = *reinterpret_cast<const float4*>(&Wt[c0 + cc][k4 * 4]);
#pragma unroll
        for (int rr = 0; rr < 8; ++rr) {
            const float4 xv =
                *reinterpret_cast<const float4*>(&xs[ty * 8 + rr][k4 * 4]);
#pragma unroll
            for (int cc = 0; cc < 4; ++cc) {
                acc[cc][rr] = fmaf(xv.x, w[cc].x, acc[cc][rr]);
                acc[cc][rr] = fmaf(xv.y, w[cc].y, acc[cc][rr]);
                acc[cc][rr] = fmaf(xv.z, w[cc].z, acc[cc][rr]);
                acc[cc][rr] = fmaf(xv.w, w[cc].w, acc[cc][rr]);
            }
        }
    }

#pragma unroll
    for (int cc = 0; cc < 4; ++cc) {
        const int col = c0 + cc;
        const int u = col % UU, gate = col / UU;
        const int oc = u * 4 + gate;                  // unit-major slot
        const float sc = (gate == 2) ? 1.0f : 0.5f;   // tanh-sigmoid prescale
#pragma unroll
        for (int rr = 0; rr < 8; ++rr)
            g_xz[(r0 + (size_t)ty * 8 + rr) * GG + oc] = sc * acc[cc][rr];
    }
}

// ---------------------------------------------------------------------------
// Kernel 2: sequential scan. One warp = 3 batches (lanes 0..29, lane=grp*10+u).
// Lane u owns unit u. Packed f32x2 gate chains: {i,f} and {g,o} pairs ->
// 20 FFMA2/step instead of 40 FFMA; each chain split in two halves.
// sigmoid via tanh.approx (z pre-scaled by 0.5). No smem/barriers in T-loop.
// ---------------------------------------------------------------------------
__global__ void lstm_scan_kernel(const float* __restrict__ R,   // [10][40]
                                 const float* __restrict__ dw,  // [10]
                                 const float* __restrict__ db,  // [1]
                                 float* __restrict__ out) {     // [256]
    const int lane = threadIdx.x;
    const int grp = lane / UU;               // 0..3 (grp 3 -> dummy lanes)
    const int u = lane - grp * UU;
    const int batch = blockIdx.x * 3 + grp;
    const bool valid = (grp < 3) && (batch < BB);
    const int bc = valid ? batch : (BB - 1); // clamp for safe loads
    const int base = grp * UU;

    // Packed recurrent weights; i,f,o columns pre-scaled by 0.5 (tanh sigmoid)
    unsigned long long Rif[UU], Rgo[UU];
#pragma unroll
    for (int j = 0; j < UU; ++j) {
        const float ri = 0.5f * R[j * GG + u];
        const float rf = 0.5f * R[j * GG + UU + u];
        const float rg =        R[j * GG + 2 * UU + u];
        const float ro = 0.5f * R[j * GG + 3 * UU + u];
        Rif[j] = pack2(ri, rf);
        Rgo[j] = pack2(rg, ro);
    }
    float dwr[UU];
#pragma unroll
    for (int j = 0; j < UU; ++j) dwr[j] = dw[j];

    // Per-lane xz stream: float4 {zi,zf,zg,zo} for unit u (pre-scaled)
    const float4* xzp =
        reinterpret_cast<const float4*>(g_xz) + (size_t)bc * TT * UU + u;

    float4 buf[8];                            // depth-8 prefetch ring
#pragma unroll
    for (int p = 0; p < 8; ++p) buf[p] = xzp[(size_t)p * UU];

    float h = 0.f, c = 0.f;

    for (int t = 0; t < TT; t += 8) {
#pragma unroll
        for (int p = 0; p < 8; ++p) {
            const float4 z4 = buf[p];
            const int tf = t + 8 + p;         // prefetch 8 steps ahead
            if (tf < TT) buf[p] = xzp[(size_t)tf * UU];

            unsigned long long zif0 = pack2(z4.x, z4.y);
            unsigned long long zgo0 = pack2(z4.z, z4.w);
            unsigned long long zif1 = 0ull, zgo1 = 0ull;

#pragma unroll
            for (int j = 0; j < UU; ++j) {
                const float hj = __shfl_sync(0xffffffffu, h, base + j);
                const unsigned long long hh = pack2(hj, hj);
                if (j < 5) {
                    zif0 = ffma2(hh, Rif[j], zif0);
                    zgo0 = ffma2(hh, Rgo[j], zgo0);
                } else {
                    zif1 = ffma2(hh, Rif[j], zif1);
                    zgo1 = ffma2(hh, Rgo[j], zgo1);
                }
            }
            float zi, zf, zg, zo;
            unpack2(fadd2(zif0, zif1), zi, zf);
            unpack2(fadd2(zgo0, zgo1), zg, zo);

            // sigmoid(2z) = 0.5*tanh(z)+0.5  (z already holds 0.5*logit)
            const float ig = fmaf(0.5f, tanh_ap(zi), 0.5f);
            const float fg = fmaf(0.5f, tanh_ap(zf), 0.5f);
            const float og = fmaf(0.5f, tanh_ap(zo), 0.5f);
            const float gg = zg * rcp_ap(1.0f + fabsf(zg));   // softsign
            c = fmaf(fg, c, ig * gg);
            const float r = rcp_ap(1.0f + fabsf(c));
            h = (og * c) * r;                                 // o * softsign(c)
        }
    }

    // Head: sigmoid(h @ dw + db)
    float logit = db[0];
#pragma unroll
    for (int j = 0; j < UU; ++j)
        logit = fmaf(__shfl_sync(0xffffffffu, h, base + j), dwr[j], logit);
    if (valid && u == 0)
        out[batch] = __fdividef(1.f, 1.f + __expf(-logit));
}

// ---------------------------------------------------------------------------
extern "C" void kernel_launch(void* const* d_in, const int* in_sizes, int n_in,
                              void* d_out, int out_size) {
    const float* x    = (const float*)d_in[0];  // [256,2048,64]
    const float* W    = (const float*)d_in[1];  // [64,40]
    const float* R    = (const float*)d_in[2];  // [10,40]
    const float* bias = (const float*)d_in[3];  // [40]
    const float* dw   = (const float*)d_in[4];  // [10,1]
    const float* db   = (const float*)d_in[5];  // [1]
    float* out = (float*)d_out;                 // [256,1]

    dim3 b1(10, 16);
    gemm_xz_kernel<<<(BB * TT) / 128, b1>>>(x, W, bias);
    lstm_scan_kernel<<<(BB + 2) / 3, 32>>>(R, dw, db, out);
}

// round 4
// speedup vs baseline: 1.7400x; 1.4538x over previous
#include <cuda_runtime.h>

// LSTM: B=256, T=2048, F=64, U=10. Gates i,f,g,o; g=softsign; h=o*softsign(c);
// head = sigmoid(h@dw+db).
//
// SINGLE fused kernel, 86 blocks x 224 threads (one block per 3 batches):
//   warps 0..5  : producers — GEMM xz = x@W+bias for this block's batches,
//                 chunk-major (64 timesteps/chunk), written to global g_xz
//                 in unit-major layout with 0.5 prescale on i,f,o gates.
//   warp 6      : consumer — sequential LSTM scan (highest wid => arbiter
//                 priority on its SMSP). Polls a volatile smem chunk counter.
// All sync is intra-CTA (named barrier for producers + threadfence_block),
// so forward progress is guaranteed and the launch is graph-capturable.

#define BB 256
#define TT 2048
#define FF 64
#define UU 10
#define GG 40
#define CH 64          // timesteps per chunk
#define NCHUNK (TT / CH)

__device__ float g_xz[(size_t)BB * TT * GG];   // 83.9 MB scratch

// ---------------------------------------------------------------------------
// packed f32x2 + MUFU helpers
// ---------------------------------------------------------------------------
__device__ __forceinline__ unsigned long long pack2(float x, float y) {
    unsigned long long d;
    asm("mov.b64 %0, {%1, %2};" : "=l"(d) : "f"(x), "f"(y));
    return d;
}
__device__ __forceinline__ void unpack2(unsigned long long a, float& x, float& y) {
    asm("mov.b64 {%0, %1}, %2;" : "=f"(x), "=f"(y) : "l"(a));
}
__device__ __forceinline__ unsigned long long ffma2(unsigned long long a,
                                                    unsigned long long b,
                                                    unsigned long long c) {
    unsigned long long d;
    asm("fma.rn.f32x2 %0, %1, %2, %3;" : "=l"(d) : "l"(a), "l"(b), "l"(c));
    return d;
}
__device__ __forceinline__ unsigned long long fadd2(unsigned long long a,
                                                    unsigned long long b) {
    unsigned long long d;
    asm("add.rn.f32x2 %0, %1, %2;" : "=l"(d) : "l"(a), "l"(b));
    return d;
}
__device__ __forceinline__ float tanh_ap(float x) {
    float r; asm("tanh.approx.f32 %0, %1;" : "=f"(r) : "f"(x)); return r;
}
__device__ __forceinline__ float rcp_ap(float x) {
    float r; asm("rcp.approx.f32 %0, %1;" : "=f"(r) : "f"(x)); return r;
}
__device__ __forceinline__ void bar_producers() {
    asm volatile("bar.sync 1, 192;" ::: "memory");
}

// ---------------------------------------------------------------------------
// scan inner: 8 steps, one warp = 3 batches (lane = grp*10+u)
// ---------------------------------------------------------------------------
__device__ __forceinline__ void scan_group8(
        const float4*& pf, float4 buf[8],
        const unsigned long long Rif[UU], const unsigned long long Rgo[UU],
        float& h, float& c, int base, bool doLoad) {
#pragma unroll
    for (int p = 0; p < 8; ++p) {
        const float4 z4 = buf[p];
        if (doLoad) buf[p] = pf[(size_t)p * UU];

        unsigned long long zif0 = pack2(z4.x, z4.y);
        unsigned long long zgo0 = pack2(z4.z, z4.w);
        unsigned long long zif1 = 0ull, zgo1 = 0ull;
#pragma unroll
        for (int j = 0; j < UU; ++j) {
            const float hj = __shfl_sync(0xffffffffu, h, base + j);
            const unsigned long long hh = pack2(hj, hj);
            if (j < 5) {
                zif0 = ffma2(hh, Rif[j], zif0);
                zgo0 = ffma2(hh, Rgo[j], zgo0);
            } else {
                zif1 = ffma2(hh, Rif[j], zif1);
                zgo1 = ffma2(hh, Rgo[j], zgo1);
            }
        }
        float zi, zf, zg, zo;
        unpack2(fadd2(zif0, zif1), zi, zf);
        unpack2(fadd2(zgo0, zgo1), zg, zo);

        const float ig = fmaf(0.5f, tanh_ap(zi), 0.5f);
        const float fg = fmaf(0.5f, tanh_ap(zf), 0.5f);
        const float og = fmaf(0.5f, tanh_ap(zo), 0.5f);
        const float gg = zg * rcp_ap(1.0f + fabsf(zg));     // softsign
        c = fmaf(fg, c, ig * gg);
        const float r = rcp_ap(1.0f + fabsf(c));
        h = (og * c) * r;                                    // o*softsign(c)
    }
    pf += 8 * UU;
}

// ---------------------------------------------------------------------------
__global__ void __launch_bounds__(224, 1) fused_lstm_kernel(
        const float* __restrict__ x,     // [256,2048,64]
        const float* __restrict__ W,     // [64,40]
        const float* __restrict__ R,     // [10,40]
        const float* __restrict__ bias,  // [40]
        const float* __restrict__ dw,    // [10]
        const float* __restrict__ db,    // [1]
        float* __restrict__ out) {       // [256]
    __shared__ float Wt[GG][FF + 4];     // W transposed (col-major rows)
    __shared__ float bs[GG];
    __shared__ volatile unsigned int counter;   // chunks completed

    const int tid = threadIdx.x;
    const int wid = tid >> 5;
    const int lane = tid & 31;

    if (tid == 0) counter = 0u;
    for (int i = tid; i < FF * GG; i += 224) {
        int k = i / GG, col = i - k * GG;
        Wt[col][k] = W[i];
    }
    if (tid < GG) bs[tid] = bias[tid];
    __syncthreads();

    if (wid < 6) {
        // ---------------- producers: warps 0..5, thread = one (b,t) row -----
        const int row = wid * 32 + lane;          // 0..191
        const int bi = row >> 6;                  // 0..2
        const int tloc = row & 63;
        int gb = blockIdx.x * 3 + bi;
        if (gb > BB - 1) gb = BB - 1;             // clamp (dup writes = same data)
        const size_t rowbase = (size_t)gb * TT + tloc;

        for (int k = 0; k < NCHUNK; ++k) {
            const size_t t = rowbase + (size_t)k * CH;
            const float4* xr = reinterpret_cast<const float4*>(x + t * FF);
            float4 xv[16];
#pragma unroll
            for (int i = 0; i < 16; ++i) xv[i] = xr[i];

            float acc[GG];
#pragma unroll
            for (int col = 0; col < GG; ++col) acc[col] = 0.f;

#pragma unroll
            for (int k4 = 0; k4 < 16; ++k4) {
                const float4 xq = xv[k4];
#pragma unroll
                for (int col = 0; col < GG; ++col) {
                    const float4 w =
                        *reinterpret_cast<const float4*>(&Wt[col][k4 * 4]);
                    float a = acc[col];
                    a = fmaf(xq.x, w.x, a);
                    a = fmaf(xq.y, w.y, a);
                    a = fmaf(xq.z, w.z, a);
                    acc[col] = fmaf(xq.w, w.w, a);
                }
            }

            // unit-major permuted store with bias + 0.5 prescale (i,f,o)
            float4* op = reinterpret_cast<float4*>(&g_xz[t * GG]);
#pragma unroll
            for (int u = 0; u < UU; ++u) {
                float4 v;
                v.x = 0.5f * (acc[u] + bs[u]);                // i
                v.y = 0.5f * (acc[10 + u] + bs[10 + u]);      // f
                v.z =        (acc[20 + u] + bs[20 + u]);      // g
                v.w = 0.5f * (acc[30 + u] + bs[30 + u]);      // o
                op[u] = v;
            }

            __threadfence_block();
            bar_producers();
            if (tid == 0) counter = (unsigned)(k + 1);
        }
    } else {
        // ---------------- consumer: warp 6 (highest wid = arbiter priority) --
        const int sl = lane;
        const int grp = sl / UU;                  // 0..3 (3 = dummy)
        const int u = sl - grp * UU;
        const int batch = blockIdx.x * 3 + grp;
        const bool valid = (grp < 3) && (batch < BB);
        const int bc = valid ? batch : (BB - 1);
        const int base = grp * UU;

        unsigned long long Rif[UU], Rgo[UU];
#pragma unroll
        for (int j = 0; j < UU; ++j) {
            const float ri = 0.5f * R[j * GG + u];
            const float rf = 0.5f * R[j * GG + UU + u];
            const float rg =        R[j * GG + 2 * UU + u];
            const float ro = 0.5f * R[j * GG + 3 * UU + u];
            Rif[j] = pack2(ri, rf);
            Rgo[j] = pack2(rg, ro);
        }
        float dwr[UU];
#pragma unroll
        for (int j = 0; j < UU; ++j) dwr[j] = dw[j];

        const float4* xzp =
            reinterpret_cast<const float4*>(g_xz) + (size_t)bc * TT * UU + u;

        // wait for chunk 0, then prime depth-8 prefetch ring
        while (counter < 1u) __nanosleep(64);
        __threadfence_block();
        __syncwarp();

        float4 buf[8];
#pragma unroll
        for (int p = 0; p < 8; ++p) buf[p] = xzp[(size_t)p * UU];
        const float4* pf = xzp + 8 * UU;

        float h = 0.f, c = 0.f;

        for (int k = 0; k < NCHUNK; ++k) {
            if (k < NCHUNK - 1) {
                // loads in this chunk prefetch into chunk k+1
                while (counter < (unsigned)(k + 2)) __nanosleep(64);
                __threadfence_block();
                __syncwarp();
                for (int g8 = 0; g8 < 8; ++g8)
                    scan_group8(pf, buf, Rif, Rgo, h, c, base, true);
            } else {
                for (int g8 = 0; g8 < 7; ++g8)
                    scan_group8(pf, buf, Rif, Rgo, h, c, base, true);
                scan_group8(pf, buf, Rif, Rgo, h, c, base, false);
            }
        }

        float logit = db[0];
#pragma unroll
        for (int j = 0; j < UU; ++j)
            logit = fmaf(__shfl_sync(0xffffffffu, h, base + j), dwr[j], logit);
        if (valid && u == 0)
            out[batch] = __fdividef(1.f, 1.f + __expf(-logit));
    }
}

// ---------------------------------------------------------------------------
extern "C" void kernel_launch(void* const* d_in, const int* in_sizes, int n_in,
                              void* d_out, int out_size) {
    const float* x    = (const float*)d_in[0];
    const float* W    = (const float*)d_in[1];
    const float* R    = (const float*)d_in[2];
    const float* bias = (const float*)d_in[3];
    const float* dw   = (const float*)d_in[4];
    const float* db   = (const float*)d_in[5];
    float* out = (float*)d_out;

    fused_lstm_kernel<<<(BB + 2) / 3, 224>>>(x, W, R, bias, dw, db, out);
}

// round 5
// speedup vs baseline: 1.9261x; 1.1070x over previous
#include <cuda_runtime.h>

// LSTM: B=256, T=2048, F=64, U=10. Gates i,f,g,o; g=softsign; h=o*softsign(c);
// head = sigmoid(h@dw+db).
//
// SINGLE fused kernel, 86 blocks x 256 threads (one block per 3 batches):
//   warps {0,1,2,4,5,6} : producers — GEMM xz = x@W+bias, chunk-major
//                         (64 t/chunk), global g_xz, unit-major layout,
//                         0.5 prescale on i,f,o gates.
//   warp 3              : exits immediately (keeps SMSP3 clear).
//   warp 7              : consumer scan — EXCLUSIVE SMSP3, highest wid.
// Sync: producers bar.sync(1,192) per chunk -> smem counter; scan polls.

#define BB 256
#define TT 2048
#define FF 64
#define UU 10
#define GG 40
#define CH 64
#define NCHUNK (TT / CH)

__device__ float g_xz[(size_t)BB * TT * GG];   // 83.9 MB scratch

__device__ __forceinline__ float tanh_ap(float x) {
    float r; asm("tanh.approx.f32 %0, %1;" : "=f"(r) : "f"(x)); return r;
}
__device__ __forceinline__ float rcp_ap(float x) {
    float r; asm("rcp.approx.f32 %0, %1;" : "=f"(r) : "f"(x)); return r;
}
__device__ __forceinline__ void bar_producers() {
    asm volatile("bar.sync 1, 192;" ::: "memory");
}

// ---------------------------------------------------------------------------
// scan inner: 8 steps. Scalar FFMA, two independent 5-deep chains per gate.
// ---------------------------------------------------------------------------
__device__ __forceinline__ void scan_group8(
        const float4*& pf, float4 buf[8],
        const float Ri[UU], const float Rf[UU],
        const float Rg[UU], const float Ro[UU],
        float& h, float& c, int base, bool doLoad) {
#pragma unroll
    for (int p = 0; p < 8; ++p) {
        const float4 z4 = buf[p];
        if (doLoad) buf[p] = pf[(size_t)p * UU];

        float hs[UU];
#pragma unroll
        for (int j = 0; j < UU; ++j)
            hs[j] = __shfl_sync(0xffffffffu, h, base + j);

        // two 5-deep chains per gate (split accumulators)
        float zi0 = fmaf(hs[0], Ri[0], z4.x), zi1 = hs[5] * Ri[5];
        float zf0 = fmaf(hs[0], Rf[0], z4.y), zf1 = hs[5] * Rf[5];
        float zg0 = fmaf(hs[0], Rg[0], z4.z), zg1 = hs[5] * Rg[5];
        float zo0 = fmaf(hs[0], Ro[0], z4.w), zo1 = hs[5] * Ro[5];
#pragma unroll
        for (int j = 1; j < 5; ++j) {
            zi0 = fmaf(hs[j], Ri[j], zi0); zi1 = fmaf(hs[5 + j], Ri[5 + j], zi1);
            zf0 = fmaf(hs[j], Rf[j], zf0); zf1 = fmaf(hs[5 + j], Rf[5 + j], zf1);
            zg0 = fmaf(hs[j], Rg[j], zg0); zg1 = fmaf(hs[5 + j], Rg[5 + j], zg1);
            zo0 = fmaf(hs[j], Ro[j], zo0); zo1 = fmaf(hs[5 + j], Ro[5 + j], zo1);
        }
        const float zi = zi0 + zi1;
        const float zf = zf0 + zf1;
        const float zg = zg0 + zg1;
        const float zo = zo0 + zo1;

        // sigmoid(2z) = 0.5*tanh(z)+0.5  (z holds 0.5*logit for i,f,o)
        const float ig = fmaf(0.5f, tanh_ap(zi), 0.5f);
        const float fg = fmaf(0.5f, tanh_ap(zf), 0.5f);
        const float og = fmaf(0.5f, tanh_ap(zo), 0.5f);
        const float gg = zg * rcp_ap(1.0f + fabsf(zg));     // softsign
        c = fmaf(fg, c, ig * gg);
        const float r = rcp_ap(1.0f + fabsf(c));
        h = (og * c) * r;                                    // o*softsign(c)
    }
    pf += 8 * UU;
}

// ---------------------------------------------------------------------------
__global__ void __launch_bounds__(256, 1) fused_lstm_kernel(
        const float* __restrict__ x,     // [256,2048,64]
        const float* __restrict__ W,     // [64,40]
        const float* __restrict__ R,     // [10,40]
        const float* __restrict__ bias,  // [40]
        const float* __restrict__ dw,    // [10]
        const float* __restrict__ db,    // [1]
        float* __restrict__ out) {       // [256]
    __shared__ float Wt[GG][FF + 4];
    __shared__ float bs[GG];
    __shared__ volatile unsigned int counter;

    const int tid = threadIdx.x;
    const int wid = tid >> 5;
    const int lane = tid & 31;

    if (tid == 0) counter = 0u;
    for (int i = tid; i < FF * GG; i += 256) {
        int k = i / GG, col = i - k * GG;
        Wt[col][k] = W[i];
    }
    if (tid < GG) bs[tid] = bias[tid];
    __syncthreads();

    if (wid == 3) return;   // keep SMSP3 exclusive for the scan warp (wid 7)

    if (wid != 7) {
        // ---- producers: wids {0,1,2,4,5,6} -> rows 0..191 -------------------
        const int pw = (wid < 3) ? wid : wid - 1;   // 0..5
        const int row = pw * 32 + lane;
        const int bi = row >> 6;
        const int tloc = row & 63;
        int gb = blockIdx.x * 3 + bi;
        if (gb > BB - 1) gb = BB - 1;   // clamp: dup writes carry same values
        const size_t rowbase = (size_t)gb * TT + tloc;

        for (int k = 0; k < NCHUNK; ++k) {
            const size_t t = rowbase + (size_t)k * CH;
            const float4* xr = reinterpret_cast<const float4*>(x + t * FF);
            float4 xv[16];
#pragma unroll
            for (int i = 0; i < 16; ++i) xv[i] = xr[i];

            float acc[GG];
#pragma unroll
            for (int col = 0; col < GG; ++col) acc[col] = 0.f;

#pragma unroll
            for (int k4 = 0; k4 < 16; ++k4) {
                const float4 xq = xv[k4];
#pragma unroll
                for (int col = 0; col < GG; ++col) {
                    const float4 w =
                        *reinterpret_cast<const float4*>(&Wt[col][k4 * 4]);
                    float a = acc[col];
                    a = fmaf(xq.x, w.x, a);
                    a = fmaf(xq.y, w.y, a);
                    a = fmaf(xq.z, w.z, a);
                    acc[col] = fmaf(xq.w, w.w, a);
                }
            }

            float4* op = reinterpret_cast<float4*>(&g_xz[t * GG]);
#pragma unroll
            for (int u = 0; u < UU; ++u) {
                float4 v;
                v.x = 0.5f * (acc[u] + bs[u]);               // i
                v.y = 0.5f * (acc[10 + u] + bs[10 + u]);     // f
                v.z =        (acc[20 + u] + bs[20 + u]);     // g
                v.w = 0.5f * (acc[30 + u] + bs[30 + u]);     // o
                op[u] = v;
            }

            __threadfence_block();
            bar_producers();
            if (tid == 0) counter = (unsigned)(k + 1);
        }
    } else {
        // ---- consumer: warp 7, exclusive SMSP3 ------------------------------
        const int grp = lane / UU;          // 0..3 (3 = dummy lanes 30,31)
        const int u = lane - grp * UU;
        const int batch = blockIdx.x * 3 + grp;
        const bool valid = (grp < 3) && (batch < BB);
        const int bc = valid ? batch : (BB - 1);
        const int base = grp * UU;

        float Ri[UU], Rf[UU], Rg[UU], Ro[UU];
#pragma unroll
        for (int j = 0; j < UU; ++j) {
            Ri[j] = 0.5f * R[j * GG + u];
            Rf[j] = 0.5f * R[j * GG + UU + u];
            Rg[j] =        R[j * GG + 2 * UU + u];
            Ro[j] = 0.5f * R[j * GG + 3 * UU + u];
        }
        float dwr[UU];
#pragma unroll
        for (int j = 0; j < UU; ++j) dwr[j] = dw[j];

        const float4* xzp =
            reinterpret_cast<const float4*>(g_xz) + (size_t)bc * TT * UU + u;

        while (counter < 1u) __nanosleep(64);
        __threadfence_block();
        __syncwarp();

        float4 buf[8];
#pragma unroll
        for (int p = 0; p < 8; ++p) buf[p] = xzp[(size_t)p * UU];
        const float4* pf = xzp + 8 * UU;

        float h = 0.f, c = 0.f;

        for (int k = 0; k < NCHUNK; ++k) {
            if (k < NCHUNK - 1) {
                while (counter < (unsigned)(k + 2)) __nanosleep(64);
                __threadfence_block();
                __syncwarp();
                for (int g8 = 0; g8 < 8; ++g8)
                    scan_group8(pf, buf, Ri, Rf, Rg, Ro, h, c, base, true);
            } else {
                for (int g8 = 0; g8 < 7; ++g8)
                    scan_group8(pf, buf, Ri, Rf, Rg, Ro, h, c, base, true);
                scan_group8(pf, buf, Ri, Rf, Rg, Ro, h, c, base, false);
            }
        }

        float logit = db[0];
#pragma unroll
        for (int j = 0; j < UU; ++j)
            logit = fmaf(__shfl_sync(0xffffffffu, h, base + j), dwr[j], logit);
        if (valid && u == 0)
            out[batch] = __fdividef(1.f, 1.f + __expf(-logit));
    }
}

// ---------------------------------------------------------------------------
extern "C" void kernel_launch(void* const* d_in, const int* in_sizes, int n_in,
                              void* d_out, int out_size) {
    const float* x    = (const float*)d_in[0];
    const float* W    = (const float*)d_in[1];
    const float* R    = (const float*)d_in[2];
    const float* bias = (const float*)d_in[3];
    const float* dw   = (const float*)d_in[4];
    const float* db   = (const float*)d_in[5];
    float* out = (float*)d_out;

    fused_lstm_kernel<<<(BB + 2) / 3, 256>>>(x, W, R, bias, dw, db, out);
}